// round 11
// baseline (speedup 1.0000x reference)
#include <cuda_runtime.h>
#include <cuda_bf16.h>
#include <math.h>
#include <stdint.h>

#define EMBED    2048
#define NEXP     64
#define TOPK     8
#define KC       32
#define NCH      64
#define TOKS_CTA 128
#define THREADS  256
#define NBLK     256
#define MARGIN   5e-5f
#define STRH     40                // halves per smem row (32 + 8 pad)

// SMEM map (bytes)
#define SM_XF     1024u            // raw x fp32: 2 buf x 128 x 32 f32 = 32768
#define SM_XB     33792u           // x bf16 split: 2 buf x 2 lvl x 128 x STRH h = 40960
#define SM_W      74752u           // W bf16 split: 2 buf x 2 lvl x 64 x STRH h = 20480
#define SM_LS     SM_XB            // logits/probs alias: 128 x 65 f32 = 33280
#define SM_CNT    95232u
#define SM_FLAGC  95488u
#define SM_FLAGL  95504u
#define SMEM_TOTAL 96256u

__device__ __align__(16) unsigned char g_wsp[NCH * 10240];  // [chunk][lvl][e][STRH] bf16
__device__ float        g_pi_part[NBLK][NEXP];
__device__ unsigned int g_cnt[NEXP];

// one-shot: split W into 2 bf16 levels, chunked layout matching smem
__global__ void prep_kernel(const float* __restrict__ w) {
    int idx = blockIdx.x * blockDim.x + threadIdx.x;   // e*2048 + k
    int e = idx >> 11, k = idx & 2047;
    int c = k >> 5, kk = k & 31;
    float f = w[idx];
    __nv_bfloat16 h0 = __float2bfloat16_rn(f);
    float r = f - __bfloat162float(h0);
    __nv_bfloat16 h1 = __float2bfloat16_rn(r);
    unsigned base = (unsigned)c * 10240u;
    unsigned off = (unsigned)(e * STRH + kk) * 2u;
    *(__nv_bfloat16*)(g_wsp + base + off)         = h0;
    *(__nv_bfloat16*)(g_wsp + base + 5120u + off) = h1;
    if (idx < NEXP) g_cnt[idx] = 0u;
}

__device__ __forceinline__ void cp_async16(unsigned saddr, const void* gaddr) {
    asm volatile("cp.async.ca.shared.global [%0], [%1], 16;" :: "r"(saddr), "l"(gaddr));
}
__device__ __forceinline__ void cp_commit() { asm volatile("cp.async.commit_group;"); }
__device__ __forceinline__ void cp_waitall() { asm volatile("cp.async.wait_group 0;" ::: "memory"); }

__device__ __forceinline__ void ldsm4(unsigned* r, unsigned addr) {
    asm volatile("ldmatrix.sync.aligned.m8n8.x4.shared.b16 {%0,%1,%2,%3}, [%4];"
                 : "=r"(r[0]), "=r"(r[1]), "=r"(r[2]), "=r"(r[3]) : "r"(addr));
}
__device__ __forceinline__ void ldsm2(unsigned* r, unsigned addr) {
    asm volatile("ldmatrix.sync.aligned.m8n8.x2.shared.b16 {%0,%1}, [%2];"
                 : "=r"(r[0]), "=r"(r[1]) : "r"(addr));
}
__device__ __forceinline__ void mma16816(float* c, const unsigned* a, const unsigned* b) {
    asm volatile(
        "mma.sync.aligned.m16n8k16.row.col.f32.bf16.bf16.f32 "
        "{%0,%1,%2,%3}, {%4,%5,%6,%7}, {%8,%9}, {%0,%1,%2,%3};"
        : "+f"(c[0]), "+f"(c[1]), "+f"(c[2]), "+f"(c[3])
        : "r"(a[0]), "r"(a[1]), "r"(a[2]), "r"(a[3]), "r"(b[0]), "r"(b[1]));
}

// proven softmax order (rounds 1/4): ascending max, expf, butterfly fold, IEEE div
__device__ void softmax64_exact(float* Lrow) {
    float lg[64];
    #pragma unroll
    for (int e = 0; e < 64; e++) lg[e] = Lrow[e];
    float mx = lg[0];
    #pragma unroll
    for (int e = 1; e < 64; e++) mx = fmaxf(mx, lg[e]);
    float ex[64];
    #pragma unroll
    for (int e = 0; e < 64; e++) ex[e] = expf(lg[e] - mx);
    float v[32];
    #pragma unroll
    for (int j = 0; j < 32; j++) v[j] = ex[j] + ex[j + 32];
    #pragma unroll
    for (int off = 16; off >= 1; off >>= 1) {
        float nv[32];
        #pragma unroll
        for (int j = 0; j < 32; j++) nv[j] = v[j] + v[j ^ off];
        #pragma unroll
        for (int j = 0; j < 32; j++) v[j] = nv[j];
    }
    float s = v[0];
    #pragma unroll
    for (int e = 0; e < 64; e++) Lrow[e] = ex[e] / s;
}

__global__ void __launch_bounds__(THREADS, 2) gate_kernel(
    const float* __restrict__ x, const float* __restrict__ w,
    float* __restrict__ out, int ntok)
{
    extern __shared__ __align__(1024) unsigned char smx[];
    const unsigned sb = (unsigned)__cvta_generic_to_shared(smx);
    const int t = threadIdx.x, lane = t & 31, wid = t >> 5;
    const long tokBase = (long)blockIdx.x * TOKS_CTA;

    if (t == 0) *(int*)(smx + SM_FLAGC) = 0;
    if (t < NEXP) *(unsigned*)(smx + SM_CNT + 4u * t) = 0u;

    float acc[8][4];
    #pragma unroll
    for (int n = 0; n < 8; n++)
        #pragma unroll
        for (int i = 0; i < 4; i++) acc[n][i] = 0.f;

    // prologue: stage chunk 0 (raw x + split W)
    {
        #pragma unroll
        for (int j = 0; j < 4; j++) {               // x: 1024 x 16B
            int f = t + j * 256;
            int r = f >> 3, c4 = f & 7;
            cp_async16(sb + SM_XF + (unsigned)f * 16u,
                       x + (tokBase + r) * EMBED + c4 * 4);
        }
        #pragma unroll
        for (int j = 0; j < 3; j++) {               // W: 640 x 16B
            int f = t + j * 256;
            if (f < 640) cp_async16(sb + SM_W + (unsigned)f * 16u, g_wsp + f * 16);
        }
        cp_commit();
    }

    const int m0 = wid * 16;
    const int arow = (lane & 7) + ((lane >> 3) & 1) * 8;
    const int acol = (lane >> 4) * 8;
    const int brow = lane & 7;
    const int bcol = ((lane >> 3) & 1) * 8;

    for (int c = 0; c < NCH; c++) {
        const int b = c & 1;
        cp_waitall();
        __syncthreads();                            // chunk c visible; prev readers done

        if (c + 1 < NCH) {
            unsigned xfd = sb + SM_XF + (unsigned)(b ^ 1) * 16384u;
            #pragma unroll
            for (int j = 0; j < 4; j++) {
                int f = t + j * 256;
                int r = f >> 3, c4 = f & 7;
                cp_async16(xfd + (unsigned)f * 16u,
                           x + (tokBase + r) * EMBED + (c + 1) * KC + c4 * 4);
            }
            unsigned wd = sb + SM_W + (unsigned)(b ^ 1) * 10240u;
            const unsigned char* ws = g_wsp + (size_t)(c + 1) * 10240u;
            #pragma unroll
            for (int j = 0; j < 3; j++) {
                int f = t + j * 256;
                if (f < 640) cp_async16(wd + (unsigned)f * 16u, ws + f * 16);
            }
            cp_commit();
        }

        // convert raw x chunk -> 2-level bf16 split (SMEM->SMEM)
        {
            const float* xf = (const float*)(smx + SM_XF + (unsigned)b * 16384u);
            unsigned char* xb0 = smx + SM_XB + (unsigned)b * 20480u;
            #pragma unroll
            for (int i = 0; i < 4; i++) {
                int f = i * 256 + t;
                int r = f >> 3, c4 = f & 7;
                float4 v = *(const float4*)(xf + r * 32 + c4 * 4);
                float fv[4] = {v.x, v.y, v.z, v.w};
                #pragma unroll
                for (int p = 0; p < 2; p++) {
                    float f0 = fv[2 * p], f1 = fv[2 * p + 1];
                    __nv_bfloat16 a0 = __float2bfloat16_rn(f0);
                    __nv_bfloat16 b0 = __float2bfloat16_rn(f1);
                    float r0 = f0 - __bfloat162float(a0);
                    float r1 = f1 - __bfloat162float(b0);
                    __nv_bfloat16 a1 = __float2bfloat16_rn(r0);
                    __nv_bfloat16 b1 = __float2bfloat16_rn(r1);
                    unsigned off = (unsigned)(r * STRH + c4 * 4 + 2 * p) * 2u;
                    __nv_bfloat162 h;
                    h.x = a0; h.y = b0; *(__nv_bfloat162*)(xb0 + off) = h;
                    h.x = a1; h.y = b1; *(__nv_bfloat162*)(xb0 + 10240u + off) = h;
                }
            }
        }
        __syncthreads();

        // MMA on chunk c
        {
            unsigned xb = sb + SM_XB + (unsigned)b * 20480u;
            unsigned wbse = sb + SM_W + (unsigned)b * 10240u;
            #pragma unroll
            for (int kb = 0; kb < KC; kb += 16) {
                unsigned Ah[4], Al[4];
                unsigned aad = xb + (unsigned)((m0 + arow) * STRH + kb + acol) * 2u;
                ldsm4(Ah, aad);
                ldsm4(Al, aad + 10240u);
                #pragma unroll
                for (int n = 0; n < 8; n++) {
                    unsigned Bh[2], Bl[2];
                    unsigned bad = wbse + (unsigned)((n * 8 + brow) * STRH + kb + bcol) * 2u;
                    ldsm2(Bh, bad);
                    ldsm2(Bl, bad + 5120u);
                    mma16816(acc[n], Ah, Bh);
                    mma16816(acc[n], Ah, Bl);
                    mma16816(acc[n], Al, Bh);
                }
            }
        }
    }
    __syncthreads();   // all ldmatrix reads done before Ls (aliases XB)

    // accumulators -> Ls logits (scalar stores: row stride 65 f32 is 4B-aligned only)
    {
        float* L = (float*)(smx + SM_LS);
        int r0 = m0 + (lane >> 2), c0 = (lane & 3) * 2;
        #pragma unroll
        for (int n = 0; n < 8; n++) {
            float* p0 = L + r0 * 65 + n * 8 + c0;
            p0[0] = acc[n][0];
            p0[1] = acc[n][1];
            float* p1 = L + (r0 + 8) * 65 + n * 8 + c0;
            p1[0] = acc[n][2];
            p1[1] = acc[n][3];
        }
    }
    __syncthreads();

    // softmax (streaming) + margin flag
    if (t < TOKS_CTA) {
        float* Lrow = (float*)(smx + SM_LS) + t * 65;
        float mx = Lrow[0];
        #pragma unroll
        for (int e = 1; e < 64; e++) mx = fmaxf(mx, Lrow[e]);
        float s = 0.f;
        #pragma unroll
        for (int e = 0; e < 64; e++) { float ex = expf(Lrow[e] - mx); Lrow[e] = ex; s += ex; }
        float inv = 1.f / s;
        #pragma unroll
        for (int e = 0; e < 64; e++) Lrow[e] *= inv;

        // nondestructive top-9 (value desc, index asc) margin test
        float pv = 3.4e38f; int pe = -1;
        float tv[9];
        #pragma unroll 1
        for (int j = 0; j < 9; j++) {
            float bv = -1.f; int be = 64;
            #pragma unroll
            for (int e = 0; e < 64; e++) {
                float v = Lrow[e];
                bool after  = (v < pv) || (v == pv && e > pe);
                bool better = (v > bv) || (v == bv && e < be);
                if (after && better) { bv = v; be = e; }
            }
            tv[j] = bv; pv = bv; pe = be;
        }
        bool flag = false;
        #pragma unroll
        for (int j = 0; j < 8; j++)
            if (tv[j] - tv[j + 1] < MARGIN) flag = true;
        if (flag) {
            int si = atomicAdd((int*)(smx + SM_FLAGC), 1);
            ((int*)(smx + SM_FLAGL))[si] = t;
        }
    }
    __syncthreads();

    // exact recompute for flagged tokens (proven ascending-K fp32 chain + proven softmax)
    int nflag = *(int*)(smx + SM_FLAGC);
    for (int fi = wid; fi < nflag; fi += 8) {
        int row = ((int*)(smx + SM_FLAGL))[fi];
        const float* xp = x + (tokBase + row) * EMBED;
        const float* w0 = w + (size_t)lane * EMBED;
        const float* w1 = w + (size_t)(lane + 32) * EMBED;
        float a0 = 0.f, a1 = 0.f;
        for (int k = 0; k < EMBED; k += 4) {
            float4 xv = *(const float4*)(xp + k);
            float4 u = *(const float4*)(w0 + k);
            float4 q = *(const float4*)(w1 + k);
            a0 = fmaf(xv.x, u.x, a0); a0 = fmaf(xv.y, u.y, a0);
            a0 = fmaf(xv.z, u.z, a0); a0 = fmaf(xv.w, u.w, a0);
            a1 = fmaf(xv.x, q.x, a1); a1 = fmaf(xv.y, q.y, a1);
            a1 = fmaf(xv.z, q.z, a1); a1 = fmaf(xv.w, q.w, a1);
        }
        float* Lrow = (float*)(smx + SM_LS) + row * 65;
        Lrow[lane] = a0; Lrow[lane + 32] = a1;
        __syncwarp();
        if (lane == 0) softmax64_exact(Lrow);
        __syncwarp();
    }
    __syncthreads();

    // Pi partials (deterministic fixed order)
    if (t < NEXP) {
        const float* L = (const float*)(smx + SM_LS);
        float s1 = 0.f;
        #pragma unroll
        for (int r = 0; r < TOKS_CTA; r++) s1 += L[r * 65 + t];
        g_pi_part[blockIdx.x][t] = s1;
    }
    __syncthreads();

    // top-8 output (ascending scan, strict > => lowest index on ties)
    if (t < TOKS_CTA) {
        float* Lrow = (float*)(smx + SM_LS) + t * 65;
        const long tok = tokBase + t;
        #pragma unroll 1
        for (int kk = 0; kk < TOPK; kk++) {
            float best = -1.f; int bi = 0;
            #pragma unroll
            for (int e = 0; e < 64; e++) {
                float v = Lrow[e];
                if (v > best) { best = v; bi = e; }
            }
            Lrow[bi] = -1.f;
            out[tok * TOPK + kk] = (float)bi;
            out[(long)ntok * TOPK + tok * TOPK + kk] = best;
            atomicAdd((unsigned*)(smx + SM_CNT + 4u * bi), 1u);
        }
    }
    __syncthreads();
    if (t < NEXP) {
        unsigned cv = *(unsigned*)(smx + SM_CNT + 4u * t);
        if (cv) atomicAdd(&g_cnt[t], cv);
    }
}

__global__ void finalize_kernel(float* __restrict__ aux, int nblocks, float ntokf) {
    int e = threadIdx.x;
    float s = 0.f;
    for (int b = 0; b < nblocks; b++) s += g_pi_part[b][e];
    float Pi = s / ntokf;
    float ce = (float)g_cnt[e] / (ntokf * (float)TOPK);
    float v = Pi * ce * (float)NEXP;
    __shared__ float red[2];
    #pragma unroll
    for (int off = 16; off; off >>= 1)
        v += __shfl_xor_sync(0xffffffffu, v, off);
    if ((e & 31) == 0) red[e >> 5] = v;
    __syncthreads();
    if (e == 0) aux[0] = (red[0] + red[1]) * 0.01f;
}

extern "C" void kernel_launch(void* const* d_in, const int* in_sizes, int n_in,
                              void* d_out, int out_size) {
    const float* x = (const float*)d_in[0];
    const float* w = (const float*)d_in[1];
    float* out = (float*)d_out;
    int ntok = in_sizes[0] / EMBED;            // 32768
    int nblocks = ntok / TOKS_CTA;             // 256
    cudaFuncSetAttribute(gate_kernel, cudaFuncAttributeMaxDynamicSharedMemorySize, SMEM_TOTAL);
    prep_kernel<<<(NEXP * EMBED) / 256, 256>>>(w);
    gate_kernel<<<nblocks, THREADS, SMEM_TOTAL>>>(x, w, out, ntok);
    finalize_kernel<<<1, 64>>>(out + (long)ntok * 2 * TOPK, nblocks, (float)ntok);
}

// round 12
// speedup vs baseline: 1.6499x; 1.6499x over previous
#include <cuda_runtime.h>
#include <math.h>

#define EMBED   2048
#define NEXP    64
#define TOPK    8
#define KC      16                 // K-chunk
#define NCHUNK  (EMBED / KC)       // 128
#define TOKS    64                 // tokens per CTA (1 warp x TPT=2)
#define NBLK    512

typedef unsigned long long u64;

__device__ float        g_wt[EMBED * NEXP];   // W transposed: [k][e]
__device__ float        g_pi_part[NBLK][NEXP];
__device__ unsigned int g_cnt[NEXP];

// One-shot per launch: transpose W into g_wt, zero counters.
__global__ void prep_kernel(const float* __restrict__ w) {
    int idx = blockIdx.x * blockDim.x + threadIdx.x;   // e*2048 + k
    int e = idx >> 11, k = idx & 2047;
    g_wt[k * NEXP + e] = w[idx];
    if (idx < NEXP) g_cnt[idx] = 0u;
}

__device__ __forceinline__ u64 ffma2(u64 a, u64 b, u64 c) {
    u64 d;
    asm("fma.rn.f32x2 %0, %1, %2, %3;" : "=l"(d) : "l"(a), "l"(b), "l"(c));
    return d;
}
__device__ __forceinline__ u64 pack2(float f) {
    u64 d;
    asm("mov.b64 %0, {%1, %1};" : "=l"(d) : "f"(f));
    return d;
}
__device__ __forceinline__ void lds_v2(u64& a, u64& b, unsigned addr) {
    asm volatile("ld.shared.v2.b64 {%0, %1}, [%2];" : "=l"(a), "=l"(b) : "r"(addr));
}
__device__ __forceinline__ void cp_async16(unsigned saddr, const void* gaddr) {
    asm volatile("cp.async.ca.shared.global [%0], [%1], 16;" :: "r"(saddr), "l"(gaddr));
}
__device__ __forceinline__ void cp_commit() { asm volatile("cp.async.commit_group;"); }
__device__ __forceinline__ void cp_wait1()  { asm volatile("cp.async.wait_group 1;" ::: "memory"); }
__device__ __forceinline__ void cp_wait0()  { asm volatile("cp.async.wait_group 0;" ::: "memory"); }

// Softmax with the proven round-4 numerics: unpacked logits (lo=even, hi=odd
// expert), ascending max, expf, butterfly fold 16..1, IEEE division.
// Output probs land in p[64] — bitwise identical to round 4's Ls values.
__device__ __forceinline__ void softmax_regs(const u64 (&a)[32], float (&p)[NEXP]) {
    float l[NEXP];
    #pragma unroll
    for (int m = 0; m < 32; m++) {
        unsigned lo, hi;
        asm("mov.b64 {%0, %1}, %2;" : "=r"(lo), "=r"(hi) : "l"(a[m]));
        l[2 * m]     = __uint_as_float(lo);
        l[2 * m + 1] = __uint_as_float(hi);
    }
    float mx = l[0];
    #pragma unroll
    for (int e = 1; e < NEXP; e++) mx = fmaxf(mx, l[e]);
    float ex[NEXP];
    #pragma unroll
    for (int e = 0; e < NEXP; e++) ex[e] = expf(l[e] - mx);
    float v[32];
    #pragma unroll
    for (int j = 0; j < 32; j++) v[j] = ex[j] + ex[j + 32];
    #pragma unroll
    for (int off = 16; off >= 1; off >>= 1) {
        float nv[32];
        #pragma unroll
        for (int j = 0; j < 32; j++) nv[j] = v[j] + v[j ^ off];
        #pragma unroll
        for (int j = 0; j < 32; j++) v[j] = nv[j];
    }
    float s = v[0];
    #pragma unroll
    for (int e = 0; e < NEXP; e++) p[e] = ex[e] / s;
}

// Non-destructive top-8: ascending scan with strict > over the SAME prob
// values round 4 scanned, exclusion-by-index == round 4's "set to -1".
// Bitwise-identical selections and weights.
__device__ __forceinline__ void top8_out(const float (&p)[NEXP], long tok, int ntok,
                                         float* __restrict__ out, unsigned* cntS) {
    int ch[TOPK];
    #pragma unroll
    for (int j = 0; j < TOPK; j++) {
        float best = -1.f; int bi = 0;
        #pragma unroll
        for (int e = 0; e < NEXP; e++) {
            bool excl = false;
            #pragma unroll
            for (int q = 0; q < TOPK; q++)
                if (q < j && ch[q] == e) excl = true;
            float vv = p[e];
            if (!excl && vv > best) { best = vv; bi = e; }
        }
        ch[j] = bi;
        out[tok * TOPK + j] = (float)bi;
        out[(long)ntok * TOPK + tok * TOPK + j] = best;
        atomicAdd(&cntS[bi], 1u);
    }
}

__global__ void __launch_bounds__(32) gate_kernel(
    const float* __restrict__ x, float* __restrict__ out, int ntok)
{
    __shared__ __align__(16) float wbuf[2][KC * NEXP];   // 2 x 4KB Wt ring
    __shared__ unsigned int cntS[NEXP];

    const int t = threadIdx.x;
    const long tok0 = (long)blockIdx.x * TOKS + 2 * t;
    const float* xr0 = x + tok0 * EMBED;
    const float* xr1 = xr0 + EMBED;
    cntS[t] = 0u; cntS[t + 32] = 0u;

    u64 acc0[32], acc1[32];
    #pragma unroll
    for (int m = 0; m < 32; m++) { acc0[m] = 0ULL; acc1[m] = 0ULL; }

    const unsigned wb[2] = {
        (unsigned)__cvta_generic_to_shared(&wbuf[0][0]),
        (unsigned)__cvta_generic_to_shared(&wbuf[1][0])
    };

    // stage Wt chunk 0
    #pragma unroll
    for (int j = 0; j < 8; j++) {
        int f = t + j * 32;
        cp_async16(wb[0] + f * 16, g_wt + f * 4);
    }
    cp_commit();

    float xa0[16], xa1[16], xn0[16], xn1[16];
    {
        #pragma unroll
        for (int i = 0; i < 4; i++) {
            float4 a = *(const float4*)(xr0 + i * 4);
            xa0[4*i] = a.x; xa0[4*i+1] = a.y; xa0[4*i+2] = a.z; xa0[4*i+3] = a.w;
            float4 b = *(const float4*)(xr1 + i * 4);
            xa1[4*i] = b.x; xa1[4*i+1] = b.y; xa1[4*i+2] = b.z; xa1[4*i+3] = b.w;
        }
    }

    for (int c = 0; c < NCHUNK; c++) {
        if (c + 1 < NCHUNK) {
            const int kc = (c + 1) * KC;
            unsigned dst = wb[(c + 1) & 1];
            #pragma unroll
            for (int j = 0; j < 8; j++) {
                int f = t + j * 32;
                cp_async16(dst + f * 16, g_wt + kc * NEXP + f * 4);
            }
            cp_commit();
            #pragma unroll
            for (int i = 0; i < 4; i++) {
                float4 a = *(const float4*)(xr0 + kc + i * 4);
                xn0[4*i] = a.x; xn0[4*i+1] = a.y; xn0[4*i+2] = a.z; xn0[4*i+3] = a.w;
                float4 b = *(const float4*)(xr1 + kc + i * 4);
                xn1[4*i] = b.x; xn1[4*i+1] = b.y; xn1[4*i+2] = b.z; xn1[4*i+3] = b.w;
            }
            cp_wait1();
        } else {
            cp_wait0();
        }
        __syncthreads();

        const unsigned base = wb[c & 1];
        #pragma unroll 4
        for (int k = 0; k < KC; k++) {
            u64 a0 = pack2(xa0[k]);
            u64 a1 = pack2(xa1[k]);
            #pragma unroll
            for (int m = 0; m < 16; m++) {
                u64 b0, b1;
                lds_v2(b0, b1, base + k * (NEXP * 4) + m * 16);
                acc0[2 * m]     = ffma2(a0, b0, acc0[2 * m]);
                acc0[2 * m + 1] = ffma2(a0, b1, acc0[2 * m + 1]);
                acc1[2 * m]     = ffma2(a1, b0, acc1[2 * m]);
                acc1[2 * m + 1] = ffma2(a1, b1, acc1[2 * m + 1]);
            }
        }
        if (c + 1 < NCHUNK) {
            #pragma unroll
            for (int i = 0; i < 16; i++) { xa0[i] = xn0[i]; xa1[i] = xn1[i]; }
        }
        __syncthreads();
    }

    // ================ register epilogue ================
    float q[NEXP];

    // token 0: softmax -> q, top-8 on q (non-destructive)
    softmax_regs(acc0, q);
    top8_out(q, tok0, ntok, out, cntS);

    // token 1: softmax -> p1, top-8, then fold into q
    {
        float p1[NEXP];
        softmax_regs(acc1, p1);
        top8_out(p1, tok0 + 1, ntok, out, cntS);
        #pragma unroll
        for (int e = 0; e < NEXP; e++) q[e] += p1[e];
    }

    // Pi partials: warp butterfly per expert (order change only affects aux,
    // tolerance 1e-3 >> 1e-7 delta)
    #pragma unroll
    for (int off = 16; off >= 1; off >>= 1) {
        #pragma unroll
        for (int e = 0; e < NEXP; e++)
            q[e] += __shfl_xor_sync(0xffffffffu, q[e], off);
    }
    if (t == 0) {
        #pragma unroll
        for (int e = 0; e < NEXP; e++)
            g_pi_part[blockIdx.x][e] = q[e];
    }
    __syncthreads();
    if (cntS[t])      atomicAdd(&g_cnt[t], cntS[t]);
    if (cntS[t + 32]) atomicAdd(&g_cnt[t + 32], cntS[t + 32]);
}

__global__ void finalize_kernel(float* __restrict__ aux, int nblocks, float ntokf) {
    int e = threadIdx.x;   // 64 threads
    float s = 0.f;
    for (int b = 0; b < nblocks; b++) s += g_pi_part[b][e];
    float Pi = s / ntokf;
    float ce = (float)g_cnt[e] / (ntokf * (float)TOPK);
    float v = Pi * ce * (float)NEXP;
    __shared__ float red[2];
    #pragma unroll
    for (int off = 16; off; off >>= 1)
        v += __shfl_xor_sync(0xffffffffu, v, off);
    if ((e & 31) == 0) red[e >> 5] = v;
    __syncthreads();
    if (e == 0) aux[0] = (red[0] + red[1]) * 0.01f;
}

extern "C" void kernel_launch(void* const* d_in, const int* in_sizes, int n_in,
                              void* d_out, int out_size) {
    const float* x = (const float*)d_in[0];
    const float* w = (const float*)d_in[1];
    float* out = (float*)d_out;
    int ntok = in_sizes[0] / EMBED;        // 32768
    int nblocks = ntok / TOKS;             // 512
    prep_kernel<<<(NEXP * EMBED) / 256, 256>>>(w);
    gate_kernel<<<nblocks, 32>>>(x, out, ntok);
    finalize_kernel<<<1, 64>>>(out + (long)ntok * 2 * TOPK, nblocks, (float)ntok);
}

// round 13
// speedup vs baseline: 2.0087x; 1.2175x over previous
#include <cuda_runtime.h>
#include <math.h>

#define EMBED   2048
#define NEXP    64
#define TOPK    8
#define KC      16                 // K-chunk
#define NCHUNK  (EMBED / KC)       // 128
#define TPT     2                  // tokens per thread
#define TOKS    64                 // tokens per CTA (32 threads x 2)
#define NBLK    512

typedef unsigned long long u64;

__device__ float        g_wt[EMBED * NEXP];   // W transposed: [k][e]
__device__ float        g_pi_part[NBLK][NEXP];
__device__ unsigned int g_cnt[NEXP];

// One-shot per launch: transpose W into g_wt, zero counters.
__global__ void prep_kernel(const float* __restrict__ w) {
    int idx = blockIdx.x * blockDim.x + threadIdx.x;   // e*2048 + k
    int e = idx >> 11, k = idx & 2047;
    g_wt[k * NEXP + e] = w[idx];
    if (idx < NEXP) g_cnt[idx] = 0u;
}

__device__ __forceinline__ u64 ffma2(u64 a, u64 b, u64 c) {
    u64 d;
    asm("fma.rn.f32x2 %0, %1, %2, %3;" : "=l"(d) : "l"(a), "l"(b), "l"(c));
    return d;
}
__device__ __forceinline__ u64 pack2(float f) {
    u64 d;
    asm("mov.b64 %0, {%1, %1};" : "=l"(d) : "f"(f));
    return d;
}
__device__ __forceinline__ void lds_v2(u64& a, u64& b, unsigned addr) {
    asm volatile("ld.shared.v2.b64 {%0, %1}, [%2];" : "=l"(a), "=l"(b) : "r"(addr));
}
__device__ __forceinline__ void cp_async16(unsigned saddr, const void* gaddr) {
    asm volatile("cp.async.ca.shared.global [%0], [%1], 16;" :: "r"(saddr), "l"(gaddr));
}
__device__ __forceinline__ void cp_commit() { asm volatile("cp.async.commit_group;"); }
__device__ __forceinline__ void cp_wait1()  { asm volatile("cp.async.wait_group 1;" ::: "memory"); }
__device__ __forceinline__ void cp_wait0()  { asm volatile("cp.async.wait_group 0;" ::: "memory"); }

__device__ __forceinline__ void load16(float (&d)[16], const float* p) {
    #pragma unroll
    for (int i = 0; i < 4; i++) {
        float4 v = *(const float4*)(p + i * 4);
        d[i * 4 + 0] = v.x; d[i * 4 + 1] = v.y; d[i * 4 + 2] = v.z; d[i * 4 + 3] = v.w;
    }
}

// Round-4-identical softmax numerics: sequential-k logits in `a`
// (lo lane = even expert, hi = odd), expf, butterfly sum (16..1), IEEE div.
__device__ __forceinline__ void softmax_row(const u64 (&a)[32], float (&p)[NEXP]) {
    float l[NEXP];
    #pragma unroll
    for (int m = 0; m < 32; m++) {
        unsigned lo, hi;
        asm("mov.b64 {%0, %1}, %2;" : "=r"(lo), "=r"(hi) : "l"(a[m]));
        l[2 * m]     = __uint_as_float(lo);
        l[2 * m + 1] = __uint_as_float(hi);
    }
    float mx = l[0];
    #pragma unroll
    for (int e = 1; e < NEXP; e++) mx = fmaxf(mx, l[e]);
    float ex[NEXP];
    #pragma unroll
    for (int e = 0; e < NEXP; e++) ex[e] = expf(l[e] - mx);
    float v[32];
    #pragma unroll
    for (int j = 0; j < 32; j++) v[j] = ex[j] + ex[j + 32];
    #pragma unroll
    for (int off = 16; off >= 1; off >>= 1) {
        float nv[32];
        #pragma unroll
        for (int j = 0; j < 32; j++) nv[j] = v[j] + v[j ^ off];
        #pragma unroll
        for (int j = 0; j < 32; j++) v[j] = nv[j];
    }
    float s = v[0];
    #pragma unroll
    for (int e = 0; e < NEXP; e++) p[e] = ex[e] / s;
}

__global__ void __launch_bounds__(32) gate_kernel(
    const float* __restrict__ x, float* __restrict__ out, int ntok)
{
    __shared__ __align__(16) float wbuf[2][KC * NEXP];   // 2 x 4KB Wt double buffer
    __shared__ float Ls[TOKS][NEXP + 1];
    __shared__ unsigned int cntS[NEXP];

    const int t = threadIdx.x;
    const long tok0 = (long)blockIdx.x * TOKS + 2 * t;
    const float* xr0 = x + tok0 * EMBED;
    const float* xr1 = xr0 + EMBED;
    cntS[t] = 0u; cntS[t + 32] = 0u;

    u64 acc0[32], acc1[32];
    #pragma unroll
    for (int m = 0; m < 32; m++) { acc0[m] = 0ULL; acc1[m] = 0ULL; }

    const unsigned wb[2] = {
        (unsigned)__cvta_generic_to_shared(&wbuf[0][0]),
        (unsigned)__cvta_generic_to_shared(&wbuf[1][0])
    };

    // stage Wt chunk 0 (contiguous 4KB)
    #pragma unroll
    for (int j = 0; j < 8; j++) {
        int f = t + j * 32;
        cp_async16(wb[0] + f * 16, g_wt + f * 4);
    }
    cp_commit();

    float xa0[16], xa1[16], xn0[16], xn1[16];
    load16(xa0, xr0); load16(xa1, xr1);

    for (int c = 0; c < NCHUNK; c++) {
        if (c + 1 < NCHUNK) {
            unsigned dst = wb[(c + 1) & 1];
            const float* src = g_wt + (c + 1) * (KC * NEXP);
            #pragma unroll
            for (int j = 0; j < 8; j++) {
                int f = t + j * 32;
                cp_async16(dst + f * 16, src + f * 4);
            }
            cp_commit();
            load16(xn0, xr0 + (c + 1) * KC);
            load16(xn1, xr1 + (c + 1) * KC);
            cp_wait1();
        } else {
            cp_wait0();
        }
        __syncwarp();

        const unsigned base = wb[c & 1];
        #pragma unroll
        for (int k = 0; k < KC; k++) {
            u64 a0 = pack2(xa0[k]);
            u64 a1 = pack2(xa1[k]);
            // 4-m blocks: load 8 expert-pair u64s, then issue 8 consecutive
            // FFMA2 on a0 followed by 8 on a1 (slot-a operand-reuse friendly).
            // Per-accumulator (a,b) sequences are in the same ascending-k
            // order as round 4 => bitwise-identical logits.
            #pragma unroll
            for (int mb = 0; mb < 4; mb++) {
                u64 b0, b1, b2, b3, b4, b5, b6, b7;
                unsigned ad = base + k * (NEXP * 4) + mb * 64;
                lds_v2(b0, b1, ad);
                lds_v2(b2, b3, ad + 16);
                lds_v2(b4, b5, ad + 32);
                lds_v2(b6, b7, ad + 48);
                int m8 = mb * 8;
                acc0[m8 + 0] = ffma2(a0, b0, acc0[m8 + 0]);
                acc0[m8 + 1] = ffma2(a0, b1, acc0[m8 + 1]);
                acc0[m8 + 2] = ffma2(a0, b2, acc0[m8 + 2]);
                acc0[m8 + 3] = ffma2(a0, b3, acc0[m8 + 3]);
                acc0[m8 + 4] = ffma2(a0, b4, acc0[m8 + 4]);
                acc0[m8 + 5] = ffma2(a0, b5, acc0[m8 + 5]);
                acc0[m8 + 6] = ffma2(a0, b6, acc0[m8 + 6]);
                acc0[m8 + 7] = ffma2(a0, b7, acc0[m8 + 7]);
                acc1[m8 + 0] = ffma2(a1, b0, acc1[m8 + 0]);
                acc1[m8 + 1] = ffma2(a1, b1, acc1[m8 + 1]);
                acc1[m8 + 2] = ffma2(a1, b2, acc1[m8 + 2]);
                acc1[m8 + 3] = ffma2(a1, b3, acc1[m8 + 3]);
                acc1[m8 + 4] = ffma2(a1, b4, acc1[m8 + 4]);
                acc1[m8 + 5] = ffma2(a1, b5, acc1[m8 + 5]);
                acc1[m8 + 6] = ffma2(a1, b6, acc1[m8 + 6]);
                acc1[m8 + 7] = ffma2(a1, b7, acc1[m8 + 7]);
            }
        }
        if (c + 1 < NCHUNK) {
            #pragma unroll
            for (int i = 0; i < 16; i++) { xa0[i] = xn0[i]; xa1[i] = xn1[i]; }
        }
        __syncwarp();
    }

    // ---------------- epilogue (round-4 verbatim) ----------------
    {
        float p[NEXP];
        softmax_row(acc0, p);
        #pragma unroll
        for (int e = 0; e < NEXP; e++) Ls[2 * t][e] = p[e];
        softmax_row(acc1, p);
        #pragma unroll
        for (int e = 0; e < NEXP; e++) Ls[2 * t + 1][e] = p[e];
    }
    __syncthreads();

    // per-CTA Pi partials (deterministic fixed order)
    {
        float s1 = 0.f, s2 = 0.f;
        #pragma unroll
        for (int r = 0; r < TOKS; r++) { s1 += Ls[r][t]; s2 += Ls[r][t + 32]; }
        g_pi_part[blockIdx.x][t] = s1;
        g_pi_part[blockIdx.x][t + 32] = s2;
    }
    __syncthreads();   // Pi reads done before top-k mutates Ls

    // top-8 per token: ascending scan, strict > => lowest index wins ties
    #pragma unroll
    for (int tt = 0; tt < TPT; tt++) {
        const int row = 2 * t + tt;
        const long tok = tok0 + tt;
        #pragma unroll 1
        for (int kk = 0; kk < TOPK; kk++) {
            float best = -1.f; int bi = 0;
            #pragma unroll
            for (int e = 0; e < NEXP; e++) {
                float v = Ls[row][e];
                if (v > best) { best = v; bi = e; }
            }
            Ls[row][bi] = -1.f;
            out[tok * TOPK + kk] = (float)bi;
            out[(long)ntok * TOPK + tok * TOPK + kk] = best;
            atomicAdd(&cntS[bi], 1u);
        }
    }
    __syncthreads();
    if (cntS[t])      atomicAdd(&g_cnt[t], cntS[t]);
    if (cntS[t + 32]) atomicAdd(&g_cnt[t + 32], cntS[t + 32]);
}

__global__ void finalize_kernel(float* __restrict__ aux, int nblocks, float ntokf) {
    int e = threadIdx.x;   // 64 threads
    float s = 0.f;
    for (int b = 0; b < nblocks; b++) s += g_pi_part[b][e];
    float Pi = s / ntokf;
    float ce = (float)g_cnt[e] / (ntokf * (float)TOPK);
    float v = Pi * ce * (float)NEXP;
    __shared__ float red[2];
    #pragma unroll
    for (int off = 16; off; off >>= 1)
        v += __shfl_xor_sync(0xffffffffu, v, off);
    if ((e & 31) == 0) red[e >> 5] = v;
    __syncthreads();
    if (e == 0) aux[0] = (red[0] + red[1]) * 0.01f;
}

extern "C" void kernel_launch(void* const* d_in, const int* in_sizes, int n_in,
                              void* d_out, int out_size) {
    const float* x = (const float*)d_in[0];
    const float* w = (const float*)d_in[1];
    float* out = (float*)d_out;
    int ntok = in_sizes[0] / EMBED;        // 32768
    int nblocks = ntok / TOKS;             // 512
    prep_kernel<<<(NEXP * EMBED) / 256, 256>>>(w);
    gate_kernel<<<nblocks, 32>>>(x, out, ntok);
    finalize_kernel<<<1, 64>>>(out + (long)ntok * 2 * TOPK, nblocks, (float)ntok);
}